// round 9
// baseline (speedup 1.0000x reference)
#include <cuda_runtime.h>
#include <cuda_bf16.h>

#define NN 100000
#define EE 600000
#define SCAN_BLK 1024
#define NBLK ((NN + SCAN_BLK - 1) / SCAN_BLK)   // 98

// ---------------- scratch (static device globals; no allocation) -------------
__device__ int   g_deg[NN];
__device__ int   g_off[NN + 1];
__device__ int   g_cur[NN];
__device__ float g_inv[NN];
__device__ int   g_src[EE];
__device__ int   g_bsum[NBLK];
__device__ float g_agg[(size_t)NN * 128];
__device__ float g_h[(size_t)NN * 128];
__device__ float g_qr[(size_t)NN * 64];   // q (cols 0..31) | r (cols 32..63)
// W1 image: [n(128)][k(256)] bf16, half0=hi, half1=lo (k<128: W1l, else W1r)
__device__ __nv_bfloat16 g_w1t[2 * 128 * 256];
// W2 image: [n(64)][k(128)] bf16, half0=hi, half1=lo (n<32: W2l col n, else W2r col n-32)
__device__ __nv_bfloat16 g_w2t[2 * 64 * 128];
__device__ int   g_is64;

// ---------------- helpers ----------------------------------------------------
__device__ __forceinline__ int load_idx(const void* ei, long long pos, int is64) {
    if (is64) return (int)((const long long*)ei)[pos];
    return ((const int*)ei)[pos];
}
__device__ __forceinline__ unsigned cvt_bf16x2(float a, float b) {
    unsigned r;
    asm("cvt.rn.bf16x2.f32 %0, %1, %2;" : "=r"(r) : "f"(b), "f"(a));
    return r;
}
__device__ __forceinline__ void mma16816(float* d, const unsigned* a, const unsigned* b) {
    asm volatile(
        "mma.sync.aligned.m16n8k16.row.col.f32.bf16.bf16.f32 "
        "{%0,%1,%2,%3}, {%4,%5,%6,%7}, {%8,%9}, {%0,%1,%2,%3};"
        : "+f"(d[0]), "+f"(d[1]), "+f"(d[2]), "+f"(d[3])
        : "r"(a[0]), "r"(a[1]), "r"(a[2]), "r"(a[3]), "r"(b[0]), "r"(b[1]));
}

// ---------------- dtype detection: int64 vs int32 edge_index -----------------
__global__ void k_detect(const unsigned long long* ei) {
    if (threadIdx.x == 0 && blockIdx.x == 0) {
        int is64 = 1;
        #pragma unroll 1
        for (int i = 0; i < 64; i++)
            if (ei[i] > 0xFFFFFFFFull) is64 = 0;
        g_is64 = is64;
    }
}

// ---------------- degree histogram -------------------------------------------
__global__ void k_zero_deg() {
    int i = blockIdx.x * blockDim.x + threadIdx.x;
    if (i < NN) g_deg[i] = 0;
}

__global__ void k_deg(const void* ei) {
    int e = blockIdx.x * blockDim.x + threadIdx.x;
    if (e < EE) {
        int is64 = g_is64;
        int dst = load_idx(ei, (long long)EE + e, is64);
        atomicAdd(&g_deg[dst], 1);
    }
}

// ---------------- chip-wide 3-phase exclusive scan ---------------------------
__global__ void k_scan_local() {
    __shared__ int warp_tot[32];
    int tid = threadIdx.x;
    int i = blockIdx.x * SCAN_BLK + tid;
    int lane = tid & 31, wid = tid >> 5;
    int v = (i < NN) ? g_deg[i] : 0;
    int inc = v;
    #pragma unroll
    for (int d = 1; d < 32; d <<= 1) {
        int t = __shfl_up_sync(0xFFFFFFFFu, inc, d);
        if (lane >= d) inc += t;
    }
    if (lane == 31) warp_tot[wid] = inc;
    __syncthreads();
    if (wid == 0) {
        int wv = warp_tot[lane];
        int winc = wv;
        #pragma unroll
        for (int d = 1; d < 32; d <<= 1) {
            int t = __shfl_up_sync(0xFFFFFFFFu, winc, d);
            if (lane >= d) winc += t;
        }
        warp_tot[lane] = winc - wv;
        if (lane == 31) g_bsum[blockIdx.x] = winc;
    }
    __syncthreads();
    if (i < NN) g_off[i] = warp_tot[wid] + inc - v;
}

__global__ void k_scan_bsum() {
    int lane = threadIdx.x;
    int carry = 0;
    for (int base = 0; base < NBLK; base += 32) {
        int idx = base + lane;
        int v = (idx < NBLK) ? g_bsum[idx] : 0;
        int inc = v;
        #pragma unroll
        for (int d = 1; d < 32; d <<= 1) {
            int t = __shfl_up_sync(0xFFFFFFFFu, inc, d);
            if (lane >= d) inc += t;
        }
        if (idx < NBLK) g_bsum[idx] = carry + inc - v;
        carry += __shfl_sync(0xFFFFFFFFu, inc, 31);
    }
    if (lane == 0) g_off[NN] = EE;
}

__global__ void k_scan_apply() {
    int i = blockIdx.x * SCAN_BLK + threadIdx.x;
    if (i < NN) {
        int excl = g_off[i] + g_bsum[blockIdx.x];
        g_off[i] = excl;
        g_cur[i] = excl;
        g_inv[i] = 1.0f / (float)max(g_deg[i], 1);
    }
}

// ---------------- CSR placement ----------------------------------------------
__global__ void k_fill(const void* ei) {
    int e = blockIdx.x * blockDim.x + threadIdx.x;
    if (e < EE) {
        int is64 = g_is64;
        int dst = load_idx(ei, (long long)EE + e, is64);
        int src = load_idx(ei, e, is64);
        int pos = atomicAdd(&g_cur[dst], 1);
        g_src[pos] = src;
    }
}

// ---------------- gather aggregation (layer 1): warp per node -----------------
__global__ void k_agg(const float* __restrict__ feat, float* __restrict__ agg) {
    int w = (blockIdx.x * blockDim.x + threadIdx.x) >> 5;
    int lane = threadIdx.x & 31;
    if (w >= NN) return;
    int s = g_off[w], e = g_off[w + 1];
    float4 acc = make_float4(0.f, 0.f, 0.f, 0.f);
    for (int i = s; i < e; i++) {
        int sn = g_src[i];
        float4 v = __ldg((const float4*)(feat + (size_t)sn * 128 + lane * 4));
        acc.x += v.x; acc.y += v.y; acc.z += v.z; acc.w += v.w;
    }
    float iv = g_inv[w];
    acc.x *= iv; acc.y *= iv; acc.z *= iv; acc.w *= iv;
    *((float4*)(agg + (size_t)w * 128 + lane * 4)) = acc;
}

// ---------------- weight prep -------------------------------------------------
__global__ void k_prepw1(const float* __restrict__ Wl, const float* __restrict__ Wr) {
    int idx = blockIdx.x * blockDim.x + threadIdx.x;
    const int total = 128 * 256;
    if (idx >= 2 * total) return;
    int half = idx >= total;
    int rem = half ? idx - total : idx;
    int n = rem >> 8;
    int k = rem & 255;
    float w = (k < 128) ? Wl[k * 128 + n] : Wr[(k - 128) * 128 + n];
    __nv_bfloat16 hi = __float2bfloat16(w);
    __nv_bfloat16 val = half ? __float2bfloat16(w - __bfloat162float(hi)) : hi;
    g_w1t[(size_t)half * total + n * 256 + k] = val;
}

__global__ void k_prepw2(const float* __restrict__ W2l, const float* __restrict__ W2r) {
    int idx = blockIdx.x * blockDim.x + threadIdx.x;
    const int total = 64 * 128;
    if (idx >= 2 * total) return;
    int half = idx >= total;
    int rem = half ? idx - total : idx;
    int n = rem >> 7;
    int k = rem & 127;
    float w = (n < 32) ? W2l[k * 32 + n] : W2r[k * 32 + (n - 32)];
    __nv_bfloat16 hi = __float2bfloat16(w);
    __nv_bfloat16 val = half ? __float2bfloat16(w - __bfloat162float(hi)) : hi;
    g_w2t[(size_t)half * total + n * 128 + k] = val;
}

// ---------------- mma.sync bf16 hi/lo split GEMM ------------------------------
// out[r, 0:BN] = A(f32, rows of 128) @ Wt^T (+ bias) ; K = KCH*32.
// A chunk k0<128 from Aagg, else from Ax. Wt rows: KB32 b32 (=2*KB32 bf16) long.
#define SSTR 20
template <int BM, int BN, int WM, int WN, int KCH, int KB32, bool BIAS, bool RELU>
__global__ void __launch_bounds__(256)
k_mma(const float* __restrict__ Aagg, const float* __restrict__ Ax,
      const __nv_bfloat16* __restrict__ Wt, const float* __restrict__ bias,
      float* __restrict__ outp) {
    __shared__ unsigned sA[2][BM * SSTR];
    __shared__ unsigned sB[2][BN * SSTR];

    const int tid = threadIdx.x;
    const int wid = tid >> 5, lane = tid & 31;
    const int lr = lane >> 2, lc = lane & 3;
    const int row0 = blockIdx.x * BM;
    constexpr int NWN = BN / WN;
    const int warp_n = wid % NWN;
    const int warp_m = wid / NWN;
    constexpr int MT = WM / 16, NT = WN / 8;

    const unsigned* Bt32 = (const unsigned*)Wt;
    constexpr int BHALF = BN * KB32;

    float acc[MT][NT][4];
    #pragma unroll
    for (int t = 0; t < MT; t++)
        #pragma unroll
        for (int u = 0; u < NT; u++)
            #pragma unroll
            for (int q = 0; q < 4; q++) acc[t][u][q] = 0.f;

    #pragma unroll 1
    for (int kc = 0; kc < KCH; kc++) {
        const int k0 = kc * 32;
        const float* Abase = (k0 < 128) ? (Aagg + k0) : (Ax + (k0 - 128));
        #pragma unroll
        for (int t = 0; t < BM * 32 / 1024; t++) {
            int id = tid + t * 256;
            int row = id >> 3;
            int c4 = id & 7;
            int rg = row0 + row;
            float4 f = (rg < NN)
                ? __ldg((const float4*)(Abase + (size_t)rg * 128 + c4 * 4))
                : make_float4(0.f, 0.f, 0.f, 0.f);
            float hx = __bfloat162float(__float2bfloat16(f.x));
            float hy = __bfloat162float(__float2bfloat16(f.y));
            float hz = __bfloat162float(__float2bfloat16(f.z));
            float hw = __bfloat162float(__float2bfloat16(f.w));
            int p = row * SSTR + c4 * 2;
            sA[0][p]     = cvt_bf16x2(f.x, f.y);
            sA[0][p + 1] = cvt_bf16x2(f.z, f.w);
            sA[1][p]     = cvt_bf16x2(f.x - hx, f.y - hy);
            sA[1][p + 1] = cvt_bf16x2(f.z - hz, f.w - hw);
        }
        #pragma unroll
        for (int id = tid; id < BN * 16; id += 256) {
            int n = id >> 4;
            int j = id & 15;
            int srcp = n * KB32 + (k0 >> 1) + j;
            sB[0][n * SSTR + j] = __ldg(&Bt32[srcp]);
            sB[1][n * SSTR + j] = __ldg(&Bt32[BHALF + srcp]);
        }
        __syncthreads();

        #pragma unroll
        for (int kh = 0; kh < 2; kh++) {
            const int base = kh * 8;
            unsigned ah[MT][4], al[MT][4];
            #pragma unroll
            for (int t = 0; t < MT; t++) {
                int r = warp_m * WM + t * 16 + lr;
                int p0 = r * SSTR + base + lc;
                int p1 = (r + 8) * SSTR + base + lc;
                ah[t][0] = sA[0][p0]; ah[t][1] = sA[0][p1];
                ah[t][2] = sA[0][p0 + 4]; ah[t][3] = sA[0][p1 + 4];
                al[t][0] = sA[1][p0]; al[t][1] = sA[1][p1];
                al[t][2] = sA[1][p0 + 4]; al[t][3] = sA[1][p1 + 4];
            }
            unsigned bh[NT][2], bl[NT][2];
            #pragma unroll
            for (int u = 0; u < NT; u++) {
                int n = warp_n * WN + u * 8 + lr;
                int p = n * SSTR + base + lc;
                bh[u][0] = sB[0][p]; bh[u][1] = sB[0][p + 4];
                bl[u][0] = sB[1][p]; bl[u][1] = sB[1][p + 4];
            }
            #pragma unroll
            for (int t = 0; t < MT; t++)
                #pragma unroll
                for (int u = 0; u < NT; u++) {
                    mma16816(acc[t][u], ah[t], bh[u]);
                    mma16816(acc[t][u], al[t], bh[u]);
                    mma16816(acc[t][u], ah[t], bl[u]);
                }
        }
        __syncthreads();
    }

    // ---- epilogue -----------------------------------------------------------
    #pragma unroll
    for (int t = 0; t < MT; t++) {
        int r = row0 + warp_m * WM + t * 16 + lr;
        #pragma unroll
        for (int u = 0; u < NT; u++) {
            int c = warp_n * WN + u * 8 + lc * 2;
            float b0 = BIAS ? __ldg(&bias[c]) : 0.f;
            float b1 = BIAS ? __ldg(&bias[c + 1]) : 0.f;
            float v0 = acc[t][u][0] + b0, v1 = acc[t][u][1] + b1;
            float v2 = acc[t][u][2] + b0, v3 = acc[t][u][3] + b1;
            if (RELU) {
                v0 = fmaxf(v0, 0.f); v1 = fmaxf(v1, 0.f);
                v2 = fmaxf(v2, 0.f); v3 = fmaxf(v3, 0.f);
            }
            if (r < NN)
                *(float2*)(outp + (size_t)r * BN + c) = make_float2(v0, v1);
            if (r + 8 < NN)
                *(float2*)(outp + (size_t)(r + 8) * BN + c) = make_float2(v2, v3);
        }
    }
}

// ---------------- final: out = inv_deg * segsum(q[src]) + r + b2 -------------
__global__ void k_out(const float* __restrict__ qr, const float* __restrict__ b2,
                      float* __restrict__ outp) {
    int w = (blockIdx.x * blockDim.x + threadIdx.x) >> 5;
    int lane = threadIdx.x & 31;
    if (w >= NN) return;
    int s = g_off[w], e = g_off[w + 1];
    float acc = 0.f;
    for (int i = s; i < e; i++) {
        int sn = g_src[i];
        acc += __ldg(&qr[(size_t)sn * 64 + lane]);
    }
    float r = __ldg(&qr[(size_t)w * 64 + 32 + lane]);
    outp[(size_t)w * 32 + lane] = g_inv[w] * acc + r + __ldg(&b2[lane]);
}

// ---------------- launch ------------------------------------------------------
extern "C" void kernel_launch(void* const* d_in, const int* in_sizes, int n_in,
                              void* d_out, int out_size) {
    const float* x   = (const float*)d_in[0];
    const void*  ei  = d_in[1];
    const float* W1l = (const float*)d_in[2];
    const float* b1  = (const float*)d_in[3];
    const float* W1r = (const float*)d_in[4];
    const float* W2l = (const float*)d_in[5];
    const float* b2  = (const float*)d_in[6];
    const float* W2r = (const float*)d_in[7];
    float* out = (float*)d_out;

    float *agg, *h, *qr;
    __nv_bfloat16 *w1t, *w2t;
    cudaGetSymbolAddress((void**)&agg, g_agg);
    cudaGetSymbolAddress((void**)&h, g_h);
    cudaGetSymbolAddress((void**)&qr, g_qr);
    cudaGetSymbolAddress((void**)&w1t, g_w1t);
    cudaGetSymbolAddress((void**)&w2t, g_w2t);

    k_detect<<<1, 32>>>((const unsigned long long*)ei);
    k_zero_deg<<<(NN + 255) / 256, 256>>>();
    k_prepw1<<<(2 * 128 * 256 + 255) / 256, 256>>>(W1l, W1r);
    k_prepw2<<<(2 * 64 * 128 + 255) / 256, 256>>>(W2l, W2r);
    k_deg<<<(EE + 255) / 256, 256>>>(ei);
    k_scan_local<<<NBLK, SCAN_BLK>>>();
    k_scan_bsum<<<1, 32>>>();
    k_scan_apply<<<NBLK, SCAN_BLK>>>();
    k_fill<<<(EE + 255) / 256, 256>>>(ei);

    // layer 1: aggregate x, then h = relu([agg|x] @ W1' + b1)
    k_agg<<<(NN * 32 + 255) / 256, 256>>>(x, agg);
    k_mma<128, 128, 32, 64, 8, 128, true, true>
        <<<(NN + 127) / 128, 256>>>(agg, x, w1t, b1, h);

    // layer 2 (reordered): [q|r] = h @ [W2l|W2r]  (K=128, reads h only)
    k_mma<256, 64, 32, 64, 4, 64, false, false>
        <<<(NN + 255) / 256, 256>>>(h, h, w2t, b2, qr);

    // final: out = inv * segsum(q[src]) + r + b2
    k_out<<<(NN * 32 + 255) / 256, 256>>>(qr, b2, out);
}

// round 11
// speedup vs baseline: 1.1332x; 1.1332x over previous
#include <cuda_runtime.h>
#include <cuda_bf16.h>

#define NN 100000
#define EE 600000
#define SCAN_BLK 1024
#define NBLK ((NN + SCAN_BLK - 1) / SCAN_BLK)   // 98

// ---------------- scratch (static device globals; no allocation) -------------
__device__ int   g_deg[NN];
__device__ int   g_off[NN + 1];
__device__ int   g_cur[NN];
__device__ float g_inv[NN];
__device__ int   g_src[EE];
__device__ int   g_bsum[NBLK];
__device__ float g_agg[(size_t)NN * 128];
__device__ float g_h[(size_t)NN * 128];
// weight images, transposed [n][k], bf16, half 0 = hi, half 1 = lo
__device__ __nv_bfloat16 g_w1t[2 * 128 * 256];
__device__ __nv_bfloat16 g_w2t[2 * 32 * 256];
__device__ int   g_is64;

// ---------------- helpers ----------------------------------------------------
__device__ __forceinline__ int load_idx(const void* ei, long long pos, int is64) {
    if (is64) return (int)((const long long*)ei)[pos];
    return ((const int*)ei)[pos];
}
__device__ __forceinline__ unsigned cvt_bf16x2(float a, float b) {
    unsigned r;
    asm("cvt.rn.bf16x2.f32 %0, %1, %2;" : "=r"(r) : "f"(b), "f"(a));
    return r;
}
__device__ __forceinline__ void mma16816(float* d, const unsigned* a, const unsigned* b) {
    asm volatile(
        "mma.sync.aligned.m16n8k16.row.col.f32.bf16.bf16.f32 "
        "{%0,%1,%2,%3}, {%4,%5,%6,%7}, {%8,%9}, {%0,%1,%2,%3};"
        : "+f"(d[0]), "+f"(d[1]), "+f"(d[2]), "+f"(d[3])
        : "r"(a[0]), "r"(a[1]), "r"(a[2]), "r"(a[3]), "r"(b[0]), "r"(b[1]));
}
__device__ __forceinline__ unsigned smem_u32(const void* p) {
    unsigned a;
    asm("{ .reg .u64 t; cvta.to.shared.u64 t, %1; cvt.u32.u64 %0, t; }"
        : "=r"(a) : "l"(p));
    return a;
}
__device__ __forceinline__ void ldsm4(unsigned& r0, unsigned& r1, unsigned& r2,
                                      unsigned& r3, unsigned addr) {
    asm volatile("ldmatrix.sync.aligned.m8n8.x4.shared.b16 {%0,%1,%2,%3}, [%4];"
                 : "=r"(r0), "=r"(r1), "=r"(r2), "=r"(r3) : "r"(addr));
}

// ---------------- dtype detection: int64 vs int32 edge_index -----------------
__global__ void k_detect(const unsigned long long* ei) {
    if (threadIdx.x == 0 && blockIdx.x == 0) {
        int is64 = 1;
        #pragma unroll 1
        for (int i = 0; i < 64; i++)
            if (ei[i] > 0xFFFFFFFFull) is64 = 0;
        g_is64 = is64;
    }
}

// ---------------- degree histogram -------------------------------------------
__global__ void k_zero_deg() {
    int i = blockIdx.x * blockDim.x + threadIdx.x;
    if (i < NN) g_deg[i] = 0;
}

__global__ void k_deg(const void* ei) {
    int e = blockIdx.x * blockDim.x + threadIdx.x;
    if (e < EE) {
        int is64 = g_is64;
        int dst = load_idx(ei, (long long)EE + e, is64);
        atomicAdd(&g_deg[dst], 1);
    }
}

// ---------------- chip-wide 3-phase exclusive scan ---------------------------
__global__ void k_scan_local() {
    __shared__ int warp_tot[32];
    int tid = threadIdx.x;
    int i = blockIdx.x * SCAN_BLK + tid;
    int lane = tid & 31, wid = tid >> 5;
    int v = (i < NN) ? g_deg[i] : 0;
    int inc = v;
    #pragma unroll
    for (int d = 1; d < 32; d <<= 1) {
        int t = __shfl_up_sync(0xFFFFFFFFu, inc, d);
        if (lane >= d) inc += t;
    }
    if (lane == 31) warp_tot[wid] = inc;
    __syncthreads();
    if (wid == 0) {
        int wv = warp_tot[lane];
        int winc = wv;
        #pragma unroll
        for (int d = 1; d < 32; d <<= 1) {
            int t = __shfl_up_sync(0xFFFFFFFFu, winc, d);
            if (lane >= d) winc += t;
        }
        warp_tot[lane] = winc - wv;
        if (lane == 31) g_bsum[blockIdx.x] = winc;
    }
    __syncthreads();
    if (i < NN) g_off[i] = warp_tot[wid] + inc - v;
}

__global__ void k_scan_bsum() {
    int lane = threadIdx.x;
    int carry = 0;
    for (int base = 0; base < NBLK; base += 32) {
        int idx = base + lane;
        int v = (idx < NBLK) ? g_bsum[idx] : 0;
        int inc = v;
        #pragma unroll
        for (int d = 1; d < 32; d <<= 1) {
            int t = __shfl_up_sync(0xFFFFFFFFu, inc, d);
            if (lane >= d) inc += t;
        }
        if (idx < NBLK) g_bsum[idx] = carry + inc - v;
        carry += __shfl_sync(0xFFFFFFFFu, inc, 31);
    }
    if (lane == 0) g_off[NN] = EE;
}

__global__ void k_scan_apply() {
    int i = blockIdx.x * SCAN_BLK + threadIdx.x;
    if (i < NN) {
        int excl = g_off[i] + g_bsum[blockIdx.x];
        g_off[i] = excl;
        g_cur[i] = excl;
        g_inv[i] = 1.0f / (float)max(g_deg[i], 1);
    }
}

// ---------------- CSR placement ----------------------------------------------
__global__ void k_fill(const void* ei) {
    int e = blockIdx.x * blockDim.x + threadIdx.x;
    if (e < EE) {
        int is64 = g_is64;
        int dst = load_idx(ei, (long long)EE + e, is64);
        int src = load_idx(ei, e, is64);
        int pos = atomicAdd(&g_cur[dst], 1);
        g_src[pos] = src;
    }
}

// ---------------- gather aggregation: warp per node --------------------------
__global__ void k_agg(const float* __restrict__ feat, float* __restrict__ agg) {
    int w = (blockIdx.x * blockDim.x + threadIdx.x) >> 5;
    int lane = threadIdx.x & 31;
    if (w >= NN) return;
    int s = g_off[w], e = g_off[w + 1];
    float4 acc = make_float4(0.f, 0.f, 0.f, 0.f);
    for (int i = s; i < e; i++) {
        int sn = g_src[i];
        float4 v = __ldg((const float4*)(feat + (size_t)sn * 128 + lane * 4));
        acc.x += v.x; acc.y += v.y; acc.z += v.z; acc.w += v.w;
    }
    float iv = g_inv[w];
    acc.x *= iv; acc.y *= iv; acc.z *= iv; acc.w *= iv;
    *((float4*)(agg + (size_t)w * 128 + lane * 4)) = acc;
}

// ---------------- weight prep: transposed bf16 hi/lo images -------------------
// wt[half][n*256 + k], k<128 -> Wl[k][n], else Wr[k-128][n]
__global__ void k_prepw(const float* __restrict__ Wl, const float* __restrict__ Wr,
                        __nv_bfloat16* __restrict__ wt, int ncols) {
    int idx = blockIdx.x * blockDim.x + threadIdx.x;
    int total = ncols * 256;
    if (idx >= 2 * total) return;
    int half = idx >= total;
    int rem = half ? idx - total : idx;
    int n = rem >> 8;
    int k = rem & 255;
    float w = (k < 128) ? Wl[k * ncols + n] : Wr[(k - 128) * ncols + n];
    __nv_bfloat16 hi = __float2bfloat16(w);
    __nv_bfloat16 val = half ? __float2bfloat16(w - __bfloat162float(hi)) : hi;
    wt[(size_t)half * total + n * 256 + k] = val;
}

// ---------------- mma.sync bf16 hi/lo split GEMM (ldmatrix fragments) --------
// out[r, 0:BN] = [Aagg | Ax](f32) @ Wt^T + bias  (K = 256, 8 chunks of 32)
// Wt: bf16 [2][BN*256] (hi, lo), n-major rows of k.
// smem: b32 rows of 16, padded to stride 20 (conflict-free LDS & ldmatrix).
#define SSTR 20
template <int BM, int BN, int WM, int WN, bool RELU>
__global__ void __launch_bounds__(256)
k_mma(const float* __restrict__ Aagg, const float* __restrict__ Ax,
      const __nv_bfloat16* __restrict__ Wt, const float* __restrict__ bias,
      float* __restrict__ outp) {
    __shared__ unsigned sA[2][BM * SSTR];
    __shared__ unsigned sB[2][BN * SSTR];

    const int tid = threadIdx.x;
    const int wid = tid >> 5, lane = tid & 31;
    const int lr = lane >> 2, lc = lane & 3;
    const int row0 = blockIdx.x * BM;
    constexpr int NWN = BN / WN;              // warps along N
    const int warp_n = wid % NWN;
    const int warp_m = wid / NWN;
    constexpr int MT = WM / 16, NT = WN / 8;  // m/n tiles per warp

    const unsigned* Bt32 = (const unsigned*)Wt;
    constexpr int BHALF = BN * 128;           // b32 offset of lo image

    // ldmatrix per-lane base indices (b32 units within a tile image)
    //   A x4: lanes 0-7 rows 0-7 k0-7 | 8-15 rows 8-15 k0-7 |
    //         16-23 rows 0-7 k8-15   | 24-31 rows 8-15 k8-15
    const unsigned aIdx0 = (unsigned)((warp_m * WM + (lane & 15)) * SSTR
                                      + (lane >> 4) * 4);
    //   B x4: lanes 0-7 n0-7 k0-7 | 8-15 n0-7 k8-15 | 16-23 n8-15 k0-7 | 24-31 n8-15 k8-15
    const unsigned bIdx0 = (unsigned)((warp_n * WN + (lane & 7) + ((lane >> 4) << 3)) * SSTR
                                      + ((lane >> 3) & 1) * 4);
    const unsigned aB0 = smem_u32(&sA[0][0]), aB1 = smem_u32(&sA[1][0]);
    const unsigned bB0 = smem_u32(&sB[0][0]), bB1 = smem_u32(&sB[1][0]);

    float acc[MT][NT][4];
    #pragma unroll
    for (int t = 0; t < MT; t++)
        #pragma unroll
        for (int u = 0; u < NT; u++)
            #pragma unroll
            for (int q = 0; q < 4; q++) acc[t][u][q] = 0.f;

    #pragma unroll 1
    for (int kc = 0; kc < 8; kc++) {
        const int k0 = kc * 32;
        // ---- stage A chunk: BM x 32 f32 -> bf16 hi/lo --------------------
        const float* Abase = (k0 < 128) ? (Aagg + k0) : (Ax + (k0 - 128));
        #pragma unroll
        for (int t = 0; t < BM * 32 / 1024; t++) {
            int id = tid + t * 256;
            int row = id >> 3;            // 8 float4 per row
            int c4 = id & 7;
            int rg = row0 + row;
            float4 f = (rg < NN)
                ? __ldg((const float4*)(Abase + (size_t)rg * 128 + c4 * 4))
                : make_float4(0.f, 0.f, 0.f, 0.f);
            float hx = __bfloat162float(__float2bfloat16(f.x));
            float hy = __bfloat162float(__float2bfloat16(f.y));
            float hz = __bfloat162float(__float2bfloat16(f.z));
            float hw = __bfloat162float(__float2bfloat16(f.w));
            int p = row * SSTR + c4 * 2;
            *(uint2*)&sA[0][p] = make_uint2(cvt_bf16x2(f.x, f.y), cvt_bf16x2(f.z, f.w));
            *(uint2*)&sA[1][p] = make_uint2(cvt_bf16x2(f.x - hx, f.y - hy),
                                            cvt_bf16x2(f.z - hz, f.w - hw));
        }
        // ---- stage B chunk: BN x 32 bf16 (hi, lo) ------------------------
        #pragma unroll
        for (int id = tid; id < BN * 16; id += 256) {
            int n = id >> 4;
            int j = id & 15;
            int srcp = n * 128 + (k0 >> 1) + j;
            sB[0][n * SSTR + j] = __ldg(&Bt32[srcp]);
            sB[1][n * SSTR + j] = __ldg(&Bt32[BHALF + srcp]);
        }
        __syncthreads();

        // ---- compute: 2 k16 steps x 3 products, ldmatrix fragments -------
        #pragma unroll
        for (int kh = 0; kh < 2; kh++) {
            unsigned ah[MT][4], al[MT][4];
            #pragma unroll
            for (int t = 0; t < MT; t++) {
                unsigned ab = (aIdx0 + t * 16 * SSTR + kh * 8) * 4;
                ldsm4(ah[t][0], ah[t][1], ah[t][2], ah[t][3], aB0 + ab);
                ldsm4(al[t][0], al[t][1], al[t][2], al[t][3], aB1 + ab);
            }
            unsigned bh[NT][2], bl[NT][2];
            #pragma unroll
            for (int u = 0; u < NT; u += 2) {
                unsigned bb = (bIdx0 + u * 8 * SSTR + kh * 8) * 4;
                ldsm4(bh[u][0], bh[u][1], bh[u + 1][0], bh[u + 1][1], bB0 + bb);
                ldsm4(bl[u][0], bl[u][1], bl[u + 1][0], bl[u + 1][1], bB1 + bb);
            }
            #pragma unroll
            for (int t = 0; t < MT; t++)
                #pragma unroll
                for (int u = 0; u < NT; u++) {
                    mma16816(acc[t][u], ah[t], bh[u]);
                    mma16816(acc[t][u], al[t], bh[u]);
                    mma16816(acc[t][u], ah[t], bl[u]);
                }
        }
        __syncthreads();
    }

    // ---- epilogue -----------------------------------------------------------
    #pragma unroll
    for (int t = 0; t < MT; t++) {
        int r = row0 + warp_m * WM + t * 16 + lr;
        #pragma unroll
        for (int u = 0; u < NT; u++) {
            int c = warp_n * WN + u * 8 + lc * 2;
            float b0 = __ldg(&bias[c]), b1 = __ldg(&bias[c + 1]);
            float v0 = acc[t][u][0] + b0, v1 = acc[t][u][1] + b1;
            float v2 = acc[t][u][2] + b0, v3 = acc[t][u][3] + b1;
            if (RELU) {
                v0 = fmaxf(v0, 0.f); v1 = fmaxf(v1, 0.f);
                v2 = fmaxf(v2, 0.f); v3 = fmaxf(v3, 0.f);
            }
            if (r < NN)
                *(float2*)(outp + (size_t)r * BN + c) = make_float2(v0, v1);
            if (r + 8 < NN)
                *(float2*)(outp + (size_t)(r + 8) * BN + c) = make_float2(v2, v3);
        }
    }
}

// ---------------- launch ------------------------------------------------------
extern "C" void kernel_launch(void* const* d_in, const int* in_sizes, int n_in,
                              void* d_out, int out_size) {
    const float* x   = (const float*)d_in[0];
    const void*  ei  = d_in[1];
    const float* W1l = (const float*)d_in[2];
    const float* b1  = (const float*)d_in[3];
    const float* W1r = (const float*)d_in[4];
    const float* W2l = (const float*)d_in[5];
    const float* b2  = (const float*)d_in[6];
    const float* W2r = (const float*)d_in[7];
    float* out = (float*)d_out;

    float *agg, *h;
    __nv_bfloat16 *w1t, *w2t;
    cudaGetSymbolAddress((void**)&agg, g_agg);
    cudaGetSymbolAddress((void**)&h, g_h);
    cudaGetSymbolAddress((void**)&w1t, g_w1t);
    cudaGetSymbolAddress((void**)&w2t, g_w2t);

    k_detect<<<1, 32>>>((const unsigned long long*)ei);
    k_zero_deg<<<(NN + 255) / 256, 256>>>();
    k_prepw<<<(2 * 128 * 256 + 255) / 256, 256>>>(W1l, W1r, w1t, 128);
    k_prepw<<<(2 * 32 * 256 + 255) / 256, 256>>>(W2l, W2r, w2t, 32);
    k_deg<<<(EE + 255) / 256, 256>>>(ei);
    k_scan_local<<<NBLK, SCAN_BLK>>>();
    k_scan_bsum<<<1, 32>>>();
    k_scan_apply<<<NBLK, SCAN_BLK>>>();
    k_fill<<<(EE + 255) / 256, 256>>>(ei);

    // layer 1: agg + tensor GEMM (bf16 hi/lo split) + relu
    k_agg<<<(NN * 32 + 255) / 256, 256>>>(x, agg);
    k_mma<128, 128, 32, 64, true>
        <<<(NN + 127) / 128, 256>>>(agg, x, w1t, b1, h);

    // layer 2: agg + tensor GEMM
    k_agg<<<(NN * 32 + 255) / 256, 256>>>(h, agg);
    k_mma<256, 32, 32, 32, false>
        <<<(NN + 255) / 256, 256>>>(agg, h, w2t, b2, out);
}

// round 15
// speedup vs baseline: 1.2666x; 1.1177x over previous
#include <cuda_runtime.h>
#include <cuda_bf16.h>

#define NN 100000
#define EE 600000
#define SCAN_BLK 1024
#define NBLK ((NN + SCAN_BLK - 1) / SCAN_BLK)   // 98

// ---------------- scratch (static device globals; no allocation) -------------
__device__ int   g_deg[NN];
__device__ int   g_off[NN + 1];
__device__ int   g_cur[NN];
__device__ float g_inv[NN];
__device__ int   g_src[EE];
__device__ int   g_bsum[NBLK];
__device__ float g_agg[(size_t)NN * 128];
__device__ float g_h[(size_t)NN * 128];
// weight images, transposed [n][k], bf16, half 0 = hi, half 1 = lo
__device__ __align__(16) __nv_bfloat16 g_w1t[2 * 128 * 256];
__device__ __align__(16) __nv_bfloat16 g_w2t[2 * 32 * 256];
__device__ int   g_is64;

// ---------------- helpers ----------------------------------------------------
__device__ __forceinline__ int load_idx(const void* ei, long long pos, int is64) {
    if (is64) return (int)((const long long*)ei)[pos];
    return ((const int*)ei)[pos];
}
__device__ __forceinline__ unsigned cvt_bf16x2(float a, float b) {
    unsigned r;
    asm("cvt.rn.bf16x2.f32 %0, %1, %2;" : "=r"(r) : "f"(b), "f"(a));
    return r;
}
__device__ __forceinline__ void mma16816(float* d, const unsigned* a, const unsigned* b) {
    asm volatile(
        "mma.sync.aligned.m16n8k16.row.col.f32.bf16.bf16.f32 "
        "{%0,%1,%2,%3}, {%4,%5,%6,%7}, {%8,%9}, {%0,%1,%2,%3};"
        : "+f"(d[0]), "+f"(d[1]), "+f"(d[2]), "+f"(d[3])
        : "r"(a[0]), "r"(a[1]), "r"(a[2]), "r"(a[3]), "r"(b[0]), "r"(b[1]));
}
__device__ __forceinline__ unsigned smem_u32(const void* p) {
    unsigned a;
    asm("{ .reg .u64 t; cvta.to.shared.u64 t, %1; cvt.u32.u64 %0, t; }"
        : "=r"(a) : "l"(p));
    return a;
}
__device__ __forceinline__ void cp_async16(unsigned daddr, const void* src) {
    asm volatile("cp.async.cg.shared.global [%0], [%1], 16;"
                 :: "r"(daddr), "l"(src));
}

// ---------------- dtype detection: int64 vs int32 edge_index -----------------
__global__ void k_detect(const unsigned long long* ei) {
    if (threadIdx.x == 0 && blockIdx.x == 0) {
        int is64 = 1;
        #pragma unroll 1
        for (int i = 0; i < 64; i++)
            if (ei[i] > 0xFFFFFFFFull) is64 = 0;
        g_is64 = is64;
    }
}

// ---------------- degree histogram -------------------------------------------
__global__ void k_zero_deg() {
    int i = blockIdx.x * blockDim.x + threadIdx.x;
    if (i < NN) g_deg[i] = 0;
}

__global__ void k_deg(const void* ei) {
    int e = blockIdx.x * blockDim.x + threadIdx.x;
    if (e < EE) {
        int is64 = g_is64;
        int dst = load_idx(ei, (long long)EE + e, is64);
        atomicAdd(&g_deg[dst], 1);
    }
}

// ---------------- chip-wide 3-phase exclusive scan ---------------------------
__global__ void k_scan_local() {
    __shared__ int warp_tot[32];
    int tid = threadIdx.x;
    int i = blockIdx.x * SCAN_BLK + tid;
    int lane = tid & 31, wid = tid >> 5;
    int v = (i < NN) ? g_deg[i] : 0;
    int inc = v;
    #pragma unroll
    for (int d = 1; d < 32; d <<= 1) {
        int t = __shfl_up_sync(0xFFFFFFFFu, inc, d);
        if (lane >= d) inc += t;
    }
    if (lane == 31) warp_tot[wid] = inc;
    __syncthreads();
    if (wid == 0) {
        int wv = warp_tot[lane];
        int winc = wv;
        #pragma unroll
        for (int d = 1; d < 32; d <<= 1) {
            int t = __shfl_up_sync(0xFFFFFFFFu, winc, d);
            if (lane >= d) winc += t;
        }
        warp_tot[lane] = winc - wv;
        if (lane == 31) g_bsum[blockIdx.x] = winc;
    }
    __syncthreads();
    if (i < NN) g_off[i] = warp_tot[wid] + inc - v;
}

__global__ void k_scan_bsum() {
    int lane = threadIdx.x;
    int carry = 0;
    for (int base = 0; base < NBLK; base += 32) {
        int idx = base + lane;
        int v = (idx < NBLK) ? g_bsum[idx] : 0;
        int inc = v;
        #pragma unroll
        for (int d = 1; d < 32; d <<= 1) {
            int t = __shfl_up_sync(0xFFFFFFFFu, inc, d);
            if (lane >= d) inc += t;
        }
        if (idx < NBLK) g_bsum[idx] = carry + inc - v;
        carry += __shfl_sync(0xFFFFFFFFu, inc, 31);
    }
    if (lane == 0) g_off[NN] = EE;
}

__global__ void k_scan_apply() {
    int i = blockIdx.x * SCAN_BLK + threadIdx.x;
    if (i < NN) {
        int excl = g_off[i] + g_bsum[blockIdx.x];
        g_off[i] = excl;
        g_cur[i] = excl;
        g_inv[i] = 1.0f / (float)max(g_deg[i], 1);
    }
}

// ---------------- CSR placement ----------------------------------------------
__global__ void k_fill(const void* ei) {
    int e = blockIdx.x * blockDim.x + threadIdx.x;
    if (e < EE) {
        int is64 = g_is64;
        int dst = load_idx(ei, (long long)EE + e, is64);
        int src = load_idx(ei, e, is64);
        int pos = atomicAdd(&g_cur[dst], 1);
        g_src[pos] = src;
    }
}

// ---------------- gather aggregation: warp per node --------------------------
__global__ void k_agg(const float* __restrict__ feat, float* __restrict__ agg) {
    int w = (blockIdx.x * blockDim.x + threadIdx.x) >> 5;
    int lane = threadIdx.x & 31;
    if (w >= NN) return;
    int s = g_off[w], e = g_off[w + 1];
    float4 acc = make_float4(0.f, 0.f, 0.f, 0.f);
    for (int i = s; i < e; i++) {
        int sn = g_src[i];
        float4 v = __ldg((const float4*)(feat + (size_t)sn * 128 + lane * 4));
        acc.x += v.x; acc.y += v.y; acc.z += v.z; acc.w += v.w;
    }
    float iv = g_inv[w];
    acc.x *= iv; acc.y *= iv; acc.z *= iv; acc.w *= iv;
    *((float4*)(agg + (size_t)w * 128 + lane * 4)) = acc;
}

// ---------------- weight prep: transposed bf16 hi/lo images -------------------
__global__ void k_prepw(const float* __restrict__ Wl, const float* __restrict__ Wr,
                        __nv_bfloat16* __restrict__ wt, int ncols) {
    int idx = blockIdx.x * blockDim.x + threadIdx.x;
    int total = ncols * 256;
    if (idx >= 2 * total) return;
    int half = idx >= total;
    int rem = half ? idx - total : idx;
    int n = rem >> 8;
    int k = rem & 255;
    float w = (k < 128) ? Wl[k * ncols + n] : Wr[(k - 128) * ncols + n];
    __nv_bfloat16 hi = __float2bfloat16(w);
    __nv_bfloat16 val = half ? __float2bfloat16(w - __bfloat162float(hi)) : hi;
    wt[(size_t)half * total + n * 256 + k] = val;
}

#define SSTR 20

// ---------------- layer-1 GEMM: software-pipelined, cp.async B ----------------
// h = relu([agg|x] @ W1t^T + b1).  BM=128, BN=128, 8 warps (WM=32, WN=64).
// dynamic smem: sA[2][2][128*SSTR] then sB[2][2][128*SSTR]  (81920 B)
#define SM1_TILE (128 * SSTR)
#define SM1_BYTES (2 * 2 * 2 * SM1_TILE * 4)
__global__ void __launch_bounds__(256)
k_mma1(const float* __restrict__ Aagg, const float* __restrict__ Ax,
       const __nv_bfloat16* __restrict__ Wt, const float* __restrict__ bias,
       float* __restrict__ outp) {
    extern __shared__ unsigned smem1[];
    unsigned (*sA)[2][SM1_TILE] = (unsigned (*)[2][SM1_TILE])smem1;
    unsigned (*sB)[2][SM1_TILE] = (unsigned (*)[2][SM1_TILE])(smem1 + 4 * SM1_TILE);

    const int tid = threadIdx.x;
    const int wid = tid >> 5, lane = tid & 31;
    const int lr = lane >> 2, lc = lane & 3;
    const int row0 = blockIdx.x * 128;
    const int warp_n = wid & 1;
    const int warp_m = wid >> 1;

    const unsigned* Bt32 = (const unsigned*)Wt;
    const int BHALF = 128 * 128;

    // this thread's A-load coords (4 float4 per chunk)
    int arow[4], ac4[4];
    #pragma unroll
    for (int t = 0; t < 4; t++) {
        int id = tid + t * 256;
        arow[t] = id >> 3;
        ac4[t] = id & 7;
    }
    // this thread's B cp.async coords (4 x 16B per chunk)
    int bhalf[4], bn[4], bj4[4];
    #pragma unroll
    for (int e = 0; e < 4; e++) {
        int idx = tid + e * 256;
        bhalf[e] = idx >> 9;
        int rem = idx & 511;
        bn[e] = rem >> 2;
        bj4[e] = rem & 3;
    }

    float acc[2][8][4];
    #pragma unroll
    for (int t = 0; t < 2; t++)
        #pragma unroll
        for (int u = 0; u < 8; u++)
            #pragma unroll
            for (int q = 0; q < 4; q++) acc[t][u][q] = 0.f;

    // ---- prologue: A chunk 0 into regs, B chunk 0 via cp.async -------------
    float4 pf[4];
    #pragma unroll
    for (int t = 0; t < 4; t++) {
        int rg = row0 + arow[t];
        pf[t] = (rg < NN) ? __ldg((const float4*)(Aagg + (size_t)rg * 128 + ac4[t] * 4))
                          : make_float4(0.f, 0.f, 0.f, 0.f);
    }
    #pragma unroll
    for (int e = 0; e < 4; e++) {
        unsigned da = smem_u32(&sB[0][bhalf[e]][bn[e] * SSTR + bj4[e] * 4]);
        cp_async16(da, Bt32 + bhalf[e] * BHALF + bn[e] * 128 + bj4[e] * 4);
    }
    asm volatile("cp.async.commit_group;");

    #pragma unroll 1
    for (int kc = 0; kc < 8; kc++) {
        const int buf = kc & 1, nbuf = buf ^ 1;
        // ---- convert & store A(kc) into sA[buf] -----------------------------
        #pragma unroll
        for (int t = 0; t < 4; t++) {
            float4 f = pf[t];
            float hx = __bfloat162float(__float2bfloat16(f.x));
            float hy = __bfloat162float(__float2bfloat16(f.y));
            float hz = __bfloat162float(__float2bfloat16(f.z));
            float hw = __bfloat162float(__float2bfloat16(f.w));
            int p = arow[t] * SSTR + ac4[t] * 2;
            *(uint2*)&sA[buf][0][p] = make_uint2(cvt_bf16x2(f.x, f.y),
                                                 cvt_bf16x2(f.z, f.w));
            *(uint2*)&sA[buf][1][p] = make_uint2(cvt_bf16x2(f.x - hx, f.y - hy),
                                                 cvt_bf16x2(f.z - hz, f.w - hw));
        }
        // ---- prefetch A(kc+1) into regs ------------------------------------
        if (kc < 7) {
            int k0n = (kc + 1) * 32;
            const float* Abase = (k0n < 128) ? (Aagg + k0n) : (Ax + (k0n - 128));
            #pragma unroll
            for (int t = 0; t < 4; t++) {
                int rg = row0 + arow[t];
                pf[t] = (rg < NN)
                    ? __ldg((const float4*)(Abase + (size_t)rg * 128 + ac4[t] * 4))
                    : make_float4(0.f, 0.f, 0.f, 0.f);
            }
        }
        asm volatile("cp.async.wait_group 0;" ::: "memory");
        __syncthreads();
        // ---- issue B(kc+1) cp.async (lands during compute) ------------------
        if (kc < 7) {
            int k0n = (kc + 1) * 32;
            #pragma unroll
            for (int e = 0; e < 4; e++) {
                unsigned da = smem_u32(&sB[nbuf][bhalf[e]][bn[e] * SSTR + bj4[e] * 4]);
                cp_async16(da, Bt32 + bhalf[e] * BHALF + bn[e] * 128 + (k0n >> 1)
                               + bj4[e] * 4);
            }
            asm volatile("cp.async.commit_group;");
        }
        // ---- compute: 2 k16 steps x 3 products ------------------------------
        #pragma unroll
        for (int kh = 0; kh < 2; kh++) {
            const int base = kh * 8;
            unsigned ah[2][4], al[2][4];
            #pragma unroll
            for (int t = 0; t < 2; t++) {
                int r = warp_m * 32 + t * 16 + lr;
                int p0 = r * SSTR + base + lc;
                int p1 = (r + 8) * SSTR + base + lc;
                ah[t][0] = sA[buf][0][p0]; ah[t][1] = sA[buf][0][p1];
                ah[t][2] = sA[buf][0][p0 + 4]; ah[t][3] = sA[buf][0][p1 + 4];
                al[t][0] = sA[buf][1][p0]; al[t][1] = sA[buf][1][p1];
                al[t][2] = sA[buf][1][p0 + 4]; al[t][3] = sA[buf][1][p1 + 4];
            }
            unsigned bh[8][2], bl[8][2];
            #pragma unroll
            for (int u = 0; u < 8; u++) {
                int n = warp_n * 64 + u * 8 + lr;
                int p = n * SSTR + base + lc;
                bh[u][0] = sB[buf][0][p]; bh[u][1] = sB[buf][0][p + 4];
                bl[u][0] = sB[buf][1][p]; bl[u][1] = sB[buf][1][p + 4];
            }
            #pragma unroll
            for (int t = 0; t < 2; t++)
                #pragma unroll
                for (int u = 0; u < 8; u++) {
                    mma16816(acc[t][u], ah[t], bh[u]);
                    mma16816(acc[t][u], al[t], bh[u]);
                    mma16816(acc[t][u], ah[t], bl[u]);
                }
        }
        // no trailing sync: next iteration writes only the other buffers
    }

    // ---- epilogue -----------------------------------------------------------
    #pragma unroll
    for (int t = 0; t < 2; t++) {
        int r = row0 + warp_m * 32 + t * 16 + lr;
        #pragma unroll
        for (int u = 0; u < 8; u++) {
            int c = warp_n * 64 + u * 8 + lc * 2;
            float b0 = __ldg(&bias[c]), b1 = __ldg(&bias[c + 1]);
            float v0 = fmaxf(acc[t][u][0] + b0, 0.f);
            float v1 = fmaxf(acc[t][u][1] + b1, 0.f);
            float v2 = fmaxf(acc[t][u][2] + b0, 0.f);
            float v3 = fmaxf(acc[t][u][3] + b1, 0.f);
            if (r < NN)
                *(float2*)(outp + (size_t)r * 128 + c) = make_float2(v0, v1);
            if (r + 8 < NN)
                *(float2*)(outp + (size_t)(r + 8) * 128 + c) = make_float2(v2, v3);
        }
    }
}

// ---------------- layer-2 GEMM: proven R6 template (scalar staging) ----------
template <int BM, int BN, int WM, int WN, bool RELU>
__global__ void __launch_bounds__(256)
k_mma(const float* __restrict__ Aagg, const float* __restrict__ Ax,
      const __nv_bfloat16* __restrict__ Wt, const float* __restrict__ bias,
      float* __restrict__ outp) {
    __shared__ unsigned sA[2][BM * SSTR];
    __shared__ unsigned sB[2][BN * SSTR];

    const int tid = threadIdx.x;
    const int wid = tid >> 5, lane = tid & 31;
    const int lr = lane >> 2, lc = lane & 3;
    const int row0 = blockIdx.x * BM;
    constexpr int NWN = BN / WN;
    const int warp_n = wid % NWN;
    const int warp_m = wid / NWN;
    constexpr int MT = WM / 16, NT = WN / 8;

    const unsigned* Bt32 = (const unsigned*)Wt;
    constexpr int BHALF = BN * 128;

    float acc[MT][NT][4];
    #pragma unroll
    for (int t = 0; t < MT; t++)
        #pragma unroll
        for (int u = 0; u < NT; u++)
            #pragma unroll
            for (int q = 0; q < 4; q++) acc[t][u][q] = 0.f;

    #pragma unroll 1
    for (int kc = 0; kc < 8; kc++) {
        const int k0 = kc * 32;
        const float* Abase = (k0 < 128) ? (Aagg + k0) : (Ax + (k0 - 128));
        #pragma unroll
        for (int t = 0; t < BM * 32 / 1024; t++) {
            int id = tid + t * 256;
            int row = id >> 3;
            int c4 = id & 7;
            int rg = row0 + row;
            float4 f = (rg < NN)
                ? __ldg((const float4*)(Abase + (size_t)rg * 128 + c4 * 4))
                : make_float4(0.f, 0.f, 0.f, 0.f);
            float hx = __bfloat162float(__float2bfloat16(f.x));
            float hy = __bfloat162float(__float2bfloat16(f.y));
            float hz = __bfloat162float(__float2bfloat16(f.z));
            float hw = __bfloat162float(__float2bfloat16(f.w));
            int p = row * SSTR + c4 * 2;
            *(uint2*)&sA[0][p] = make_uint2(cvt_bf16x2(f.x, f.y), cvt_bf16x2(f.z, f.w));
            *(uint2*)&sA[1][p] = make_uint2(cvt_bf16x2(f.x - hx, f.y - hy),
                                            cvt_bf16x2(f.z - hz, f.w - hw));
        }
        #pragma unroll
        for (int id = tid; id < BN * 16; id += 256) {
            int n = id >> 4;
            int j = id & 15;
            int srcp = n * 128 + (k0 >> 1) + j;
            sB[0][n * SSTR + j] = __ldg(&Bt32[srcp]);
            sB[1][n * SSTR + j] = __ldg(&Bt32[BHALF + srcp]);
        }
        __syncthreads();

        #pragma unroll
        for (int kh = 0; kh < 2; kh++) {
            const int base = kh * 8;
            unsigned ah[MT][4], al[MT][4];
            #pragma unroll
            for (int t = 0; t < MT; t++) {
                int r = warp_m * WM + t * 16 + lr;
                int p0 = r * SSTR + base + lc;
                int p1 = (r + 8) * SSTR + base + lc;
                ah[t][0] = sA[0][p0]; ah[t][1] = sA[0][p1];
                ah[t][2] = sA[0][p0 + 4]; ah[t][3] = sA[0][p1 + 4];
                al[t][0] = sA[1][p0]; al[t][1] = sA[1][p1];
                al[t][2] = sA[1][p0 + 4]; al[t][3] = sA[1][p1 + 4];
            }
            unsigned bh[NT][2], bl[NT][2];
            #pragma unroll
            for (int u = 0; u < NT; u++) {
                int n = warp_n * WN + u * 8 + lr;
                int p = n * SSTR + base + lc;
                bh[u][0] = sB[0][p]; bh[u][1] = sB[0][p + 4];
                bl[u][0] = sB[1][p]; bl[u][1] = sB[1][p + 4];
            }
            #pragma unroll
            for (int t = 0; t < MT; t++)
                #pragma unroll
                for (int u = 0; u < NT; u++) {
                    mma16816(acc[t][u], ah[t], bh[u]);
                    mma16816(acc[t][u], al[t], bh[u]);
                    mma16816(acc[t][u], ah[t], bl[u]);
                }
        }
        __syncthreads();
    }

    #pragma unroll
    for (int t = 0; t < MT; t++) {
        int r = row0 + warp_m * WM + t * 16 + lr;
        #pragma unroll
        for (int u = 0; u < NT; u++) {
            int c = warp_n * WN + u * 8 + lc * 2;
            float b0 = __ldg(&bias[c]), b1 = __ldg(&bias[c + 1]);
            float v0 = acc[t][u][0] + b0, v1 = acc[t][u][1] + b1;
            float v2 = acc[t][u][2] + b0, v3 = acc[t][u][3] + b1;
            if (RELU) {
                v0 = fmaxf(v0, 0.f); v1 = fmaxf(v1, 0.f);
                v2 = fmaxf(v2, 0.f); v3 = fmaxf(v3, 0.f);
            }
            if (r < NN)
                *(float2*)(outp + (size_t)r * BN + c) = make_float2(v0, v1);
            if (r + 8 < NN)
                *(float2*)(outp + (size_t)(r + 8) * BN + c) = make_float2(v2, v3);
        }
    }
}

// ---------------- launch ------------------------------------------------------
extern "C" void kernel_launch(void* const* d_in, const int* in_sizes, int n_in,
                              void* d_out, int out_size) {
    const float* x   = (const float*)d_in[0];
    const void*  ei  = d_in[1];
    const float* W1l = (const float*)d_in[2];
    const float* b1  = (const float*)d_in[3];
    const float* W1r = (const float*)d_in[4];
    const float* W2l = (const float*)d_in[5];
    const float* b2  = (const float*)d_in[6];
    const float* W2r = (const float*)d_in[7];
    float* out = (float*)d_out;

    float *agg, *h;
    __nv_bfloat16 *w1t, *w2t;
    cudaGetSymbolAddress((void**)&agg, g_agg);
    cudaGetSymbolAddress((void**)&h, g_h);
    cudaGetSymbolAddress((void**)&w1t, g_w1t);
    cudaGetSymbolAddress((void**)&w2t, g_w2t);

    cudaFuncSetAttribute(k_mma1, cudaFuncAttributeMaxDynamicSharedMemorySize,
                         SM1_BYTES);

    k_detect<<<1, 32>>>((const unsigned long long*)ei);
    k_zero_deg<<<(NN + 255) / 256, 256>>>();
    k_prepw<<<(2 * 128 * 256 + 255) / 256, 256>>>(W1l, W1r, w1t, 128);
    k_prepw<<<(2 * 32 * 256 + 255) / 256, 256>>>(W2l, W2r, w2t, 32);
    k_deg<<<(EE + 255) / 256, 256>>>(ei);
    k_scan_local<<<NBLK, SCAN_BLK>>>();
    k_scan_bsum<<<1, 32>>>();
    k_scan_apply<<<NBLK, SCAN_BLK>>>();
    k_fill<<<(EE + 255) / 256, 256>>>(ei);

    // layer 1: agg + pipelined tensor GEMM + relu
    k_agg<<<(NN * 32 + 255) / 256, 256>>>(x, agg);
    k_mma1<<<(NN + 127) / 128, 256, SM1_BYTES>>>(agg, x, w1t, b1, h);

    // layer 2: agg + tensor GEMM (proven R6 config)
    k_agg<<<(NN * 32 + 255) / 256, 256>>>(h, agg);
    k_mma<256, 32, 32, 32, false>
        <<<(NN + 255) / 256, 256>>>(agg, h, w2t, b2, out);
}